// round 3
// baseline (speedup 1.0000x reference)
#include <cuda_runtime.h>
#include <math.h>

#define D_MODEL 1024
#define NH 16
#define HD 64
#define BB 2
#define SS 2048
#define MROWS (BB*SS)   // 4096

// Scratch (allocation-free: __device__ globals)
__device__ float g_q[MROWS*D_MODEL];     // [B,H,S,Dh]
__device__ float g_k[MROWS*D_MODEL];     // [B,H,S,Dh]
__device__ float g_v[MROWS*D_MODEL];     // [B,H,S,Dh]
__device__ float g_attn[(size_t)MROWS*D_MODEL];  // [B,S,D] (heads recombined)

// ---------------------------------------------------------------------------
// SGEMM: C[M,N] = A[M,K] @ W[N,K]^T + bias   (M=4096, N=K=1024)
// mode 0/1/2: write q/k/v scratch in [B,H,S,Dh] layout
// mode 3:     A = g_attn, plain write to Cout (d_out)
// ---------------------------------------------------------------------------
#define BM 128
#define BN 128
#define BKK 16

__global__ __launch_bounds__(256)
void sgemm_kernel(const float* __restrict__ A,
                  const float* __restrict__ W,
                  const float* __restrict__ bias,
                  float* __restrict__ Cout,
                  int mode)
{
    __shared__ float As[BKK][BM + 4];
    __shared__ float Bs[BKK][BN + 4];

    const int tid = threadIdx.x;
    const int bm  = blockIdx.y * BM;
    const int bn  = blockIdx.x * BN;

    const float* Ap = (mode == 3) ? g_attn : A;
    float* Cp;
    if      (mode == 0) Cp = g_q;
    else if (mode == 1) Cp = g_k;
    else if (mode == 2) Cp = g_v;
    else                Cp = Cout;

    const int ar = tid >> 2;            // 0..63
    const int ac = (tid & 3) << 2;      // 0,4,8,12
    const int tx = tid & 15;
    const int ty = tid >> 4;

    float acc[8][8];
    #pragma unroll
    for (int i = 0; i < 8; i++)
        #pragma unroll
        for (int j = 0; j < 8; j++)
            acc[i][j] = 0.f;

    for (int k0 = 0; k0 < D_MODEL; k0 += BKK) {
        #pragma unroll
        for (int r = 0; r < BM; r += 64) {
            float4 a4 = *(const float4*)(Ap + (size_t)(bm + ar + r) * D_MODEL + k0 + ac);
            As[ac+0][ar+r] = a4.x; As[ac+1][ar+r] = a4.y;
            As[ac+2][ar+r] = a4.z; As[ac+3][ar+r] = a4.w;
            float4 b4 = *(const float4*)(W + (size_t)(bn + ar + r) * D_MODEL + k0 + ac);
            Bs[ac+0][ar+r] = b4.x; Bs[ac+1][ar+r] = b4.y;
            Bs[ac+2][ar+r] = b4.z; Bs[ac+3][ar+r] = b4.w;
        }
        __syncthreads();

        #pragma unroll
        for (int kk = 0; kk < BKK; kk++) {
            float ra[8], rb[8];
            *(float4*)&ra[0] = *(const float4*)&As[kk][ty * 8];
            *(float4*)&ra[4] = *(const float4*)&As[kk][ty * 8 + 4];
            *(float4*)&rb[0] = *(const float4*)&Bs[kk][tx * 8];
            *(float4*)&rb[4] = *(const float4*)&Bs[kk][tx * 8 + 4];
            #pragma unroll
            for (int i = 0; i < 8; i++)
                #pragma unroll
                for (int j = 0; j < 8; j++)
                    acc[i][j] = fmaf(ra[i], rb[j], acc[i][j]);
        }
        __syncthreads();
    }

    // epilogue: bias + layout
    #pragma unroll
    for (int i = 0; i < 8; i++) {
        int m = bm + ty * 8 + i;
        #pragma unroll
        for (int j = 0; j < 8; j++) {
            int n = bn + tx * 8 + j;
            float vv = acc[i][j] + bias[n];
            if (mode <= 2) {
                int b = m >> 11;            // m / SS
                int s = m & (SS - 1);
                int h = n >> 6;             // n / HD
                int d = n & (HD - 1);
                Cp[ (((size_t)b * NH + h) * SS + s) * HD + d ] = vv;
            } else {
                Cp[(size_t)m * D_MODEL + n] = vv;
            }
        }
    }
}

// ---------------------------------------------------------------------------
// Flash-style attention, fp32. 1 block = (b, h, 64-query tile); 64 threads,
// 1 thread = 1 query row. K/V share one smem buffer (two-phase per tile) to
// stay under the 48KB static smem limit. Scores staged in stride-65 smem
// (bank = (t+j)%32 -> conflict-free for lockstep row access).
// ---------------------------------------------------------------------------
#define QT 64
#define KT 64

__global__ __launch_bounds__(64)
void attn_kernel(const int* __restrict__ mask)
{
    __shared__ float KV[KT][HD];        // 16KB, reused for K then V
    __shared__ float Ss[QT][KT + 1];    // mask flags -> scores -> probs

    const int t  = threadIdx.x;         // query row within tile
    const int q0 = blockIdx.x * QT;
    const int h  = blockIdx.y;
    const int b  = blockIdx.z;
    const float scale = 0.125f;         // 1/sqrt(64)

    const float* qbase = g_q + (((size_t)b * NH + h) * SS) * HD;
    const float* kbase = g_k + (((size_t)b * NH + h) * SS) * HD;
    const float* vbase = g_v + (((size_t)b * NH + h) * SS) * HD;
    const int*   mbase = mask + (size_t)q0 * SS;

    // own query row into registers
    float qr[HD];
    #pragma unroll
    for (int d4 = 0; d4 < HD / 4; d4++) {
        float4 v4 = *(const float4*)(qbase + (size_t)(q0 + t) * HD + d4 * 4);
        qr[d4*4+0] = v4.x; qr[d4*4+1] = v4.y; qr[d4*4+2] = v4.z; qr[d4*4+3] = v4.w;
    }

    float acc[HD];
    #pragma unroll
    for (int d = 0; d < HD; d++) acc[d] = 0.f;
    float mrun = -1e30f, lrun = 0.f;

    for (int k0 = 0; k0 < SS; k0 += KT) {
        __syncthreads();   // prior tile fully consumed before overwrites

        // cooperative load: K tile -> KV, mask tile -> Ss (as float flags)
        #pragma unroll
        for (int i = 0; i < 16; i++) {
            int lin = i * 64 + t;        // 0..1023
            int row = lin >> 4;          // 0..63
            int c4  = (lin & 15) * 4;    // 0..60
            *(float4*)&KV[row][c4] = *(const float4*)(kbase + (size_t)(k0 + row) * HD + c4);
            int4 mv = *(const int4*)(mbase + (size_t)row * SS + k0 + c4);
            Ss[row][c4+0] = (float)mv.x; Ss[row][c4+1] = (float)mv.y;
            Ss[row][c4+2] = (float)mv.z; Ss[row][c4+3] = (float)mv.w;
        }
        __syncthreads();

        // scores for own row (K rows broadcast across threads)
        float mnew = mrun;
        for (int j = 0; j < KT; j++) {
            float s = 0.f;
            #pragma unroll
            for (int d4 = 0; d4 < 16; d4++) {
                float4 kv = *(const float4*)&KV[j][d4 * 4];
                s = fmaf(qr[d4*4+0], kv.x, s);
                s = fmaf(qr[d4*4+1], kv.y, s);
                s = fmaf(qr[d4*4+2], kv.z, s);
                s = fmaf(qr[d4*4+3], kv.w, s);
            }
            float flag = Ss[t][j];
            s = (flag != 0.f) ? s * scale : -10000.f;
            Ss[t][j] = s;
            mnew = fmaxf(mnew, s);
        }

        // online softmax rescale
        float alpha = __expf(mrun - mnew);
        lrun *= alpha;
        #pragma unroll
        for (int d = 0; d < HD; d++) acc[d] *= alpha;

        float psum = 0.f;
        for (int j = 0; j < KT; j++) {
            float p = __expf(Ss[t][j] - mnew);
            Ss[t][j] = p;
            psum += p;
        }
        lrun += psum;
        mrun = mnew;

        __syncthreads();
        // load V tile over KV
        #pragma unroll
        for (int i = 0; i < 16; i++) {
            int lin = i * 64 + t;
            int row = lin >> 4;
            int c4  = (lin & 15) * 4;
            *(float4*)&KV[row][c4] = *(const float4*)(vbase + (size_t)(k0 + row) * HD + c4);
        }
        __syncthreads();

        // O += P @ V
        for (int j = 0; j < KT; j++) {
            float p = Ss[t][j];
            #pragma unroll
            for (int d4 = 0; d4 < 16; d4++) {
                float4 vv = *(const float4*)&KV[j][d4 * 4];
                acc[d4*4+0] = fmaf(p, vv.x, acc[d4*4+0]);
                acc[d4*4+1] = fmaf(p, vv.y, acc[d4*4+1]);
                acc[d4*4+2] = fmaf(p, vv.z, acc[d4*4+2]);
                acc[d4*4+3] = fmaf(p, vv.w, acc[d4*4+3]);
            }
        }
    }

    // normalize + write heads-recombined layout [B,S,D]
    float inv = 1.f / lrun;
    float* outp = g_attn + ((size_t)b * SS + q0 + t) * D_MODEL + h * HD;
    #pragma unroll
    for (int d4 = 0; d4 < 16; d4++) {
        float4 o;
        o.x = acc[d4*4+0] * inv; o.y = acc[d4*4+1] * inv;
        o.z = acc[d4*4+2] * inv; o.w = acc[d4*4+3] * inv;
        *(float4*)(outp + d4 * 4) = o;
    }
}

// ---------------------------------------------------------------------------
extern "C" void kernel_launch(void* const* d_in, const int* in_sizes, int n_in,
                              void* d_out, int out_size)
{
    const float* q    = (const float*)d_in[0];
    const float* k    = (const float*)d_in[1];
    const float* v    = (const float*)d_in[2];
    const int*   mask = (const int*)  d_in[3];
    const float* wq   = (const float*)d_in[4];
    const float* bq   = (const float*)d_in[5];
    const float* wk   = (const float*)d_in[6];
    const float* bk   = (const float*)d_in[7];
    const float* wv   = (const float*)d_in[8];
    const float* bv   = (const float*)d_in[9];
    const float* wo   = (const float*)d_in[10];
    const float* bo   = (const float*)d_in[11];
    float* out = (float*)d_out;

    dim3 gg(D_MODEL / BN, MROWS / BM);   // (8, 32)
    sgemm_kernel<<<gg, 256>>>(q, wq, bq, nullptr, 0);
    sgemm_kernel<<<gg, 256>>>(k, wk, bk, nullptr, 1);
    sgemm_kernel<<<gg, 256>>>(v, wv, bv, nullptr, 2);
    attn_kernel<<<dim3(SS / QT, NH, BB), 64>>>(mask);
    sgemm_kernel<<<gg, 256>>>(nullptr, wo, bo, out, 3);
}

// round 6
// speedup vs baseline: 1.1080x; 1.1080x over previous
#include <cuda_runtime.h>
#include <cstdint>
#include <math.h>

#define D_MODEL 1024
#define NH 16
#define HD 64
#define BB 2
#define SS 2048
#define MROWS (BB*SS)   // 4096

// Scratch (allocation-free: __device__ globals)
__device__ float g_q[(size_t)MROWS*D_MODEL];     // [B,H,S,Dh]
__device__ float g_k[(size_t)MROWS*D_MODEL];     // [B,H,S,Dh]
__device__ float g_v[(size_t)MROWS*D_MODEL];     // [B,H,S,Dh]
__device__ float g_attn[(size_t)MROWS*D_MODEL];  // [B,S,D]

// ============================================================================
// helpers
// ============================================================================
__device__ __forceinline__ float tf32_hi(float x) {
    return __uint_as_float(__float_as_uint(x) & 0xFFFFE000u);
}

// mma.sync m16n8k8 tf32: D += A*B  (A row-major 16x8, B col-major 8x8)
#define MMA_TF32(d0,d1,d2,d3, a0,a1,a2,a3, b0,b1) \
    asm volatile( \
        "mma.sync.aligned.m16n8k8.row.col.f32.tf32.tf32.f32 " \
        "{%0,%1,%2,%3}, {%4,%5,%6,%7}, {%8,%9}, {%0,%1,%2,%3};" \
        : "+f"(d0), "+f"(d1), "+f"(d2), "+f"(d3) \
        : "r"(a0), "r"(a1), "r"(a2), "r"(a3), "r"(b0), "r"(b1))

// packed f32x2 math (valid on base sm_100 — verified by R5 ptxas output)
#define FMA2(d, a, b, c) asm("fma.rn.f32x2 %0, %1, %2, %3;" : "=l"(d) : "l"(a), "l"(b), "l"(c))
#define MUL2(d, a, b)    asm("mul.rn.f32x2 %0, %1, %2;"     : "=l"(d) : "l"(a), "l"(b))
__device__ __forceinline__ unsigned long long pk2(float a, float b) {
    unsigned long long r;
    asm("mov.b64 %0, {%1, %2};" : "=l"(r) : "r"(__float_as_uint(a)), "r"(__float_as_uint(b)));
    return r;
}
__device__ __forceinline__ float2 upk2(unsigned long long v) {
    uint32_t a, b;
    asm("mov.b64 {%0, %1}, %2;" : "=r"(a), "=r"(b) : "l"(v));
    return make_float2(__uint_as_float(a), __uint_as_float(b));
}

// ============================================================================
// Split-tf32 tensor-core GEMM: C[M,N] = A[M,K] @ W[N,K]^T + bias
// M=4096, N=K=1024. Block tile 128x128, K-chunk 32. 256 threads = 8 warps
// (4x2); warp tile 32x64 = 2x8 m16n8 accum tiles. 3 mma products per tile
// (ahi*bhi + ahi*blo + alo*bhi) restore ~fp32 accuracy.
// mode 0/1/2: write q/k/v scratch in [B,H,S,Dh]; mode 3: g_attn -> Cout.
// ============================================================================
#define BK 32
#define AST 36                          // smem row stride (floats), pad 4
#define GEMM_SMEM (4 * 128 * AST * 4)   // 73728 B

__global__ __launch_bounds__(256)
void tc_gemm(const float* __restrict__ A, const float* __restrict__ W,
             const float* __restrict__ bias, float* __restrict__ Cout, int mode)
{
    extern __shared__ __align__(16) float smf[];
    float* Ah = smf;
    float* Al = Ah + 128 * AST;
    float* Bh = Al + 128 * AST;
    float* Bl = Bh + 128 * AST;

    const int tid  = threadIdx.x;
    const int wid  = tid >> 5;
    const int lane = tid & 31;
    const int wm   = (wid & 3) << 5;    // warp M offset: 0,32,64,96
    const int wn   = (wid >> 2) << 6;   // warp N offset: 0,64
    const int gr   = lane >> 2;         // group row 0..7
    const int gc   = lane & 3;          // thread in group 0..3

    const float* Ap = (mode == 3) ? g_attn : A;
    float* Cp = (mode == 0) ? g_q : (mode == 1) ? g_k : (mode == 2) ? g_v : Cout;

    const int bm = blockIdx.y * 128;
    const int bn = blockIdx.x * 128;

    float acc[2][8][4];
    #pragma unroll
    for (int mt = 0; mt < 2; mt++)
        #pragma unroll
        for (int nt = 0; nt < 8; nt++)
            #pragma unroll
            for (int r = 0; r < 4; r++)
                acc[mt][nt][r] = 0.f;

    for (int k0 = 0; k0 < D_MODEL; k0 += BK) {
        __syncthreads();   // prior chunk fully consumed

        // load chunk: A rows [bm,bm+128) x k [k0,k0+32), W rows [bn,bn+128)
        // split each value into tf32-hi (mask) + residual-lo (mask of diff)
        #pragma unroll
        for (int i = 0; i < 4; i++) {
            int lin = i * 256 + tid;          // 0..1023 float4 units
            int row = lin >> 3;               // 0..127
            int c4  = (lin & 7) << 2;         // 0..28
            int so  = row * AST + c4;

            float4 a = *(const float4*)(Ap + (size_t)(bm + row) * D_MODEL + k0 + c4);
            float4 ah, al;
            ah.x = tf32_hi(a.x); al.x = tf32_hi(a.x - ah.x);
            ah.y = tf32_hi(a.y); al.y = tf32_hi(a.y - ah.y);
            ah.z = tf32_hi(a.z); al.z = tf32_hi(a.z - ah.z);
            ah.w = tf32_hi(a.w); al.w = tf32_hi(a.w - ah.w);
            *(float4*)(Ah + so) = ah;
            *(float4*)(Al + so) = al;

            float4 b = *(const float4*)(W + (size_t)(bn + row) * D_MODEL + k0 + c4);
            float4 bh, bl;
            bh.x = tf32_hi(b.x); bl.x = tf32_hi(b.x - bh.x);
            bh.y = tf32_hi(b.y); bl.y = tf32_hi(b.y - bh.y);
            bh.z = tf32_hi(b.z); bl.z = tf32_hi(b.z - bh.z);
            bh.w = tf32_hi(b.w); bl.w = tf32_hi(b.w - bh.w);
            *(float4*)(Bh + so) = bh;
            *(float4*)(Bl + so) = bl;
        }
        __syncthreads();

        #pragma unroll
        for (int ks = 0; ks < 4; ks++) {
            const int kk = ks * 8;

            uint32_t ahi[2][4], alo[2][4];
            #pragma unroll
            for (int mt = 0; mt < 2; mt++) {
                int r0 = (wm + mt * 16 + gr) * AST + kk + gc;
                int r8 = r0 + 8 * AST;
                ahi[mt][0] = __float_as_uint(Ah[r0]);
                ahi[mt][1] = __float_as_uint(Ah[r8]);
                ahi[mt][2] = __float_as_uint(Ah[r0 + 4]);
                ahi[mt][3] = __float_as_uint(Ah[r8 + 4]);
                alo[mt][0] = __float_as_uint(Al[r0]);
                alo[mt][1] = __float_as_uint(Al[r8]);
                alo[mt][2] = __float_as_uint(Al[r0 + 4]);
                alo[mt][3] = __float_as_uint(Al[r8 + 4]);
            }
            uint32_t bhi[8][2], blo[8][2];
            #pragma unroll
            for (int nt = 0; nt < 8; nt++) {
                int n0 = (wn + nt * 8 + gr) * AST + kk + gc;
                bhi[nt][0] = __float_as_uint(Bh[n0]);
                bhi[nt][1] = __float_as_uint(Bh[n0 + 4]);
                blo[nt][0] = __float_as_uint(Bl[n0]);
                blo[nt][1] = __float_as_uint(Bl[n0 + 4]);
            }

            #pragma unroll
            for (int mt = 0; mt < 2; mt++)
                #pragma unroll
                for (int nt = 0; nt < 8; nt++) {
                    float* d = acc[mt][nt];
                    MMA_TF32(d[0], d[1], d[2], d[3],
                             alo[mt][0], alo[mt][1], alo[mt][2], alo[mt][3],
                             bhi[nt][0], bhi[nt][1]);
                    MMA_TF32(d[0], d[1], d[2], d[3],
                             ahi[mt][0], ahi[mt][1], ahi[mt][2], ahi[mt][3],
                             blo[nt][0], blo[nt][1]);
                    MMA_TF32(d[0], d[1], d[2], d[3],
                             ahi[mt][0], ahi[mt][1], ahi[mt][2], ahi[mt][3],
                             bhi[nt][0], bhi[nt][1]);
                }
        }
    }

    // epilogue: c0 (row, col), c1 (row, col+1), c2 (row+8, col), c3 (row+8, col+1)
    #pragma unroll
    for (int mt = 0; mt < 2; mt++) {
        #pragma unroll
        for (int nt = 0; nt < 8; nt++) {
            int m0 = bm + wm + mt * 16 + gr;
            int n0 = bn + wn + nt * 8 + gc * 2;
            #pragma unroll
            for (int half = 0; half < 2; half++) {     // row, row+8
                int m = m0 + half * 8;
                #pragma unroll
                for (int cc = 0; cc < 2; cc++) {       // col, col+1
                    int n = n0 + cc;
                    float v = acc[mt][nt][half * 2 + cc] + bias[n];
                    if (mode <= 2) {
                        int b = m >> 11;
                        int s = m & (SS - 1);
                        int h = n >> 6;
                        int d = n & (HD - 1);
                        Cp[(((size_t)b * NH + h) * SS + s) * HD + d] = v;
                    } else {
                        Cp[(size_t)m * D_MODEL + n] = v;
                    }
                }
            }
        }
    }
}

// ============================================================================
// Flash attention, fp32 with packed f32x2 math.
// Block = 128 threads = 128 query rows (QT=128); K/V tile KT=64, shared buffer.
// ============================================================================
#define QT 128
#define KT 64
#define ATTN_SMEM (KT*HD*4 + QT*(KT+1)*4)   // 16384 + 33280 = 49664

__global__ __launch_bounds__(128)
void attn_kernel(const int* __restrict__ mask)
{
    extern __shared__ __align__(16) char sm2[];
    float (*KV)[HD]     = (float(*)[HD])sm2;                 // 16KB (K then V)
    float (*Ss)[KT + 1] = (float(*)[KT + 1])(sm2 + KT*HD*4); // mask -> scores -> probs

    const int t  = threadIdx.x;            // query row in tile
    const int q0 = blockIdx.x * QT;
    const int h  = blockIdx.y;
    const int b  = blockIdx.z;
    const float scale = 0.125f;

    const float* qbase = g_q + ((size_t)(b * NH + h) * SS) * HD;
    const float* kbase = g_k + ((size_t)(b * NH + h) * SS) * HD;
    const float* vbase = g_v + ((size_t)(b * NH + h) * SS) * HD;
    const int*   mbase = mask + (size_t)q0 * SS;

    // own query row, packed as 32 f32x2
    unsigned long long qp[32];
    const unsigned long long* qrow =
        (const unsigned long long*)(qbase + (size_t)(q0 + t) * HD);
    #pragma unroll
    for (int i = 0; i < 32; i++) qp[i] = qrow[i];

    unsigned long long accp[32];
    #pragma unroll
    for (int i = 0; i < 32; i++) accp[i] = 0ULL;   // (0.f, 0.f)
    float mrun = -1e30f, lrun = 0.f;

    for (int k0 = 0; k0 < SS; k0 += KT) {
        __syncthreads();   // prior tile consumed

        // K tile (64x64 f32): 1024 float4 / 128 threads
        #pragma unroll
        for (int i = 0; i < 8; i++) {
            int lin = i * 128 + t;
            int row = lin >> 4;
            int c4  = (lin & 15) << 2;
            *(float4*)&KV[row][c4] = *(const float4*)(kbase + (size_t)(k0 + row) * HD + c4);
        }
        // mask tile (128x64 int): 2048 int4 / 128 threads
        #pragma unroll
        for (int i = 0; i < 16; i++) {
            int lin = i * 128 + t;
            int row = lin >> 4;
            int c4  = (lin & 15) << 2;
            int4 mv = *(const int4*)(mbase + (size_t)row * SS + k0 + c4);
            Ss[row][c4+0] = (float)mv.x; Ss[row][c4+1] = (float)mv.y;
            Ss[row][c4+2] = (float)mv.z; Ss[row][c4+3] = (float)mv.w;
        }
        __syncthreads();

        // scores (broadcast K rows; 4 independent packed chains)
        float mnew = mrun;
        for (int j = 0; j < KT; j++) {
            const unsigned long long* kk = (const unsigned long long*)KV[j];
            unsigned long long s0 = 0, s1 = 0, s2 = 0, s3 = 0;
            #pragma unroll
            for (int d = 0; d < 8; d++) {
                FMA2(s0, qp[d*4+0], kk[d*4+0], s0);
                FMA2(s1, qp[d*4+1], kk[d*4+1], s1);
                FMA2(s2, qp[d*4+2], kk[d*4+2], s2);
                FMA2(s3, qp[d*4+3], kk[d*4+3], s3);
            }
            float2 f0 = upk2(s0), f1 = upk2(s1), f2 = upk2(s2), f3 = upk2(s3);
            float s = ((f0.x + f0.y) + (f1.x + f1.y)) + ((f2.x + f2.y) + (f3.x + f3.y));
            float flag = Ss[t][j];
            s = (flag != 0.f) ? s * scale : -10000.f;
            Ss[t][j] = s;
            mnew = fmaxf(mnew, s);
        }

        // online softmax
        float alpha = __expf(mrun - mnew);
        lrun *= alpha;
        unsigned long long a2 = pk2(alpha, alpha);
        #pragma unroll
        for (int i = 0; i < 32; i++) MUL2(accp[i], accp[i], a2);

        float ps = 0.f;
        for (int j = 0; j < KT; j++) {
            float p = __expf(Ss[t][j] - mnew);
            Ss[t][j] = p;
            ps += p;
        }
        lrun += ps;
        mrun = mnew;

        __syncthreads();
        // V tile over KV
        #pragma unroll
        for (int i = 0; i < 8; i++) {
            int lin = i * 128 + t;
            int row = lin >> 4;
            int c4  = (lin & 15) << 2;
            *(float4*)&KV[row][c4] = *(const float4*)(vbase + (size_t)(k0 + row) * HD + c4);
        }
        __syncthreads();

        // O += P @ V (packed)
        for (int j = 0; j < KT; j++) {
            float p = Ss[t][j];
            unsigned long long p2 = pk2(p, p);
            const unsigned long long* vv = (const unsigned long long*)KV[j];
            #pragma unroll
            for (int i = 0; i < 32; i++) FMA2(accp[i], p2, vv[i], accp[i]);
        }
    }

    // normalize + write [B,S,D]
    float inv = 1.f / lrun;
    unsigned long long i2 = pk2(inv, inv);
    unsigned long long* outp =
        (unsigned long long*)(g_attn + ((size_t)b * SS + q0 + t) * D_MODEL + h * HD);
    #pragma unroll
    for (int i = 0; i < 32; i++) {
        unsigned long long r;
        MUL2(r, accp[i], i2);
        outp[i] = r;
    }
}

// ============================================================================
extern "C" void kernel_launch(void* const* d_in, const int* in_sizes, int n_in,
                              void* d_out, int out_size)
{
    const float* q    = (const float*)d_in[0];
    const float* k    = (const float*)d_in[1];
    const float* v    = (const float*)d_in[2];
    const int*   mask = (const int*)  d_in[3];
    const float* wq   = (const float*)d_in[4];
    const float* bq   = (const float*)d_in[5];
    const float* wk   = (const float*)d_in[6];
    const float* bk   = (const float*)d_in[7];
    const float* wv   = (const float*)d_in[8];
    const float* bv   = (const float*)d_in[9];
    const float* wo   = (const float*)d_in[10];
    const float* bo   = (const float*)d_in[11];
    float* out = (float*)d_out;

    // Unconditional (no static guards): deterministic, non-stream, capture-safe.
    cudaFuncSetAttribute(tc_gemm, cudaFuncAttributeMaxDynamicSharedMemorySize, GEMM_SMEM);
    cudaFuncSetAttribute(attn_kernel, cudaFuncAttributeMaxDynamicSharedMemorySize, ATTN_SMEM);

    dim3 gg(D_MODEL / 128, MROWS / 128);   // (8, 32)
    tc_gemm<<<gg, 256, GEMM_SMEM>>>(q, wq, bq, nullptr, 0);
    tc_gemm<<<gg, 256, GEMM_SMEM>>>(k, wk, bk, nullptr, 1);
    tc_gemm<<<gg, 256, GEMM_SMEM>>>(v, wv, bv, nullptr, 2);
    attn_kernel<<<dim3(SS / QT, NH, BB), 128, ATTN_SMEM>>>(mask);
    tc_gemm<<<gg, 256, GEMM_SMEM>>>(nullptr, wo, bo, out, 3);
}

// round 7
// speedup vs baseline: 1.9890x; 1.7951x over previous
#include <cuda_runtime.h>
#include <cuda_bf16.h>
#include <cstdint>
#include <math.h>

#define D_MODEL 1024
#define NH 16
#define HD 64
#define BB 2
#define SS 2048
#define MROWS (BB*SS)   // 4096

// Scratch (allocation-free: __device__ globals)
__device__ float g_q[(size_t)MROWS*D_MODEL];     // [B,H,S,Dh]
__device__ float g_k[(size_t)MROWS*D_MODEL];     // [B,H,S,Dh]
__device__ float g_v[(size_t)MROWS*D_MODEL];     // [B,H,S,Dh]
__device__ float g_attn[(size_t)MROWS*D_MODEL];  // [B,S,D]

// ============================================================================
// helpers
// ============================================================================
__device__ __forceinline__ float tf32_hi(float x) {
    return __uint_as_float(__float_as_uint(x) & 0xFFFFE000u);
}

// mma.sync m16n8k8 tf32: D += A*B  (A row-major 16x8, B col-major 8x8)
#define MMA_TF32(d0,d1,d2,d3, a0,a1,a2,a3, b0,b1) \
    asm volatile( \
        "mma.sync.aligned.m16n8k8.row.col.f32.tf32.tf32.f32 " \
        "{%0,%1,%2,%3}, {%4,%5,%6,%7}, {%8,%9}, {%0,%1,%2,%3};" \
        : "+f"(d0), "+f"(d1), "+f"(d2), "+f"(d3) \
        : "r"(a0), "r"(a1), "r"(a2), "r"(a3), "r"(b0), "r"(b1))

// mma.sync m16n8k16 bf16: D += A*B (A row-major 16x16, B col-major 16x8)
#define MMA_BF16(dd, a0,a1,a2,a3, b0,b1) \
    asm volatile( \
        "mma.sync.aligned.m16n8k16.row.col.f32.bf16.bf16.f32 " \
        "{%0,%1,%2,%3}, {%4,%5,%6,%7}, {%8,%9}, {%0,%1,%2,%3};" \
        : "+f"((dd)[0]), "+f"((dd)[1]), "+f"((dd)[2]), "+f"((dd)[3]) \
        : "r"(a0), "r"(a1), "r"(a2), "r"(a3), "r"(b0), "r"(b1))

__device__ __forceinline__ uint32_t pack_bf2(__nv_bfloat16 a, __nv_bfloat16 b) {
    __nv_bfloat162 v;
    v.x = a; v.y = b;
    return *(uint32_t*)&v;
}
// split (x,y) into packed bf16x2 hi + residual lo
__device__ __forceinline__ void bsplit2(float x, float y, uint32_t& hi, uint32_t& lo) {
    __nv_bfloat16 hx = __float2bfloat16_rn(x);
    __nv_bfloat16 hy = __float2bfloat16_rn(y);
    __nv_bfloat16 lx = __float2bfloat16_rn(x - __bfloat162float(hx));
    __nv_bfloat16 ly = __float2bfloat16_rn(y - __bfloat162float(hy));
    hi = pack_bf2(hx, hy);
    lo = pack_bf2(lx, ly);
}

// ============================================================================
// Split-tf32 tensor-core GEMM (unchanged from R6): C = A @ W^T + bias
// ============================================================================
#define BK 32
#define AST 36
#define GEMM_SMEM (4 * 128 * AST * 4)

__global__ __launch_bounds__(256)
void tc_gemm(const float* __restrict__ A, const float* __restrict__ W,
             const float* __restrict__ bias, float* __restrict__ Cout, int mode)
{
    extern __shared__ __align__(16) float smf[];
    float* Ah = smf;
    float* Al = Ah + 128 * AST;
    float* Bh = Al + 128 * AST;
    float* Bl = Bh + 128 * AST;

    const int tid  = threadIdx.x;
    const int wid  = tid >> 5;
    const int lane = tid & 31;
    const int wm   = (wid & 3) << 5;
    const int wn   = (wid >> 2) << 6;
    const int gr   = lane >> 2;
    const int gc   = lane & 3;

    const float* Ap = (mode == 3) ? g_attn : A;
    float* Cp = (mode == 0) ? g_q : (mode == 1) ? g_k : (mode == 2) ? g_v : Cout;

    const int bm = blockIdx.y * 128;
    const int bn = blockIdx.x * 128;

    float acc[2][8][4];
    #pragma unroll
    for (int mt = 0; mt < 2; mt++)
        #pragma unroll
        for (int nt = 0; nt < 8; nt++)
            #pragma unroll
            for (int r = 0; r < 4; r++)
                acc[mt][nt][r] = 0.f;

    for (int k0 = 0; k0 < D_MODEL; k0 += BK) {
        __syncthreads();
        #pragma unroll
        for (int i = 0; i < 4; i++) {
            int lin = i * 256 + tid;
            int row = lin >> 3;
            int c4  = (lin & 7) << 2;
            int so  = row * AST + c4;

            float4 a = *(const float4*)(Ap + (size_t)(bm + row) * D_MODEL + k0 + c4);
            float4 ah, al;
            ah.x = tf32_hi(a.x); al.x = tf32_hi(a.x - ah.x);
            ah.y = tf32_hi(a.y); al.y = tf32_hi(a.y - ah.y);
            ah.z = tf32_hi(a.z); al.z = tf32_hi(a.z - ah.z);
            ah.w = tf32_hi(a.w); al.w = tf32_hi(a.w - ah.w);
            *(float4*)(Ah + so) = ah;
            *(float4*)(Al + so) = al;

            float4 b = *(const float4*)(W + (size_t)(bn + row) * D_MODEL + k0 + c4);
            float4 bh, bl;
            bh.x = tf32_hi(b.x); bl.x = tf32_hi(b.x - bh.x);
            bh.y = tf32_hi(b.y); bl.y = tf32_hi(b.y - bh.y);
            bh.z = tf32_hi(b.z); bl.z = tf32_hi(b.z - bh.z);
            bh.w = tf32_hi(b.w); bl.w = tf32_hi(b.w - bh.w);
            *(float4*)(Bh + so) = bh;
            *(float4*)(Bl + so) = bl;
        }
        __syncthreads();

        #pragma unroll
        for (int ks = 0; ks < 4; ks++) {
            const int kk = ks * 8;
            uint32_t ahi[2][4], alo[2][4];
            #pragma unroll
            for (int mt = 0; mt < 2; mt++) {
                int r0 = (wm + mt * 16 + gr) * AST + kk + gc;
                int r8 = r0 + 8 * AST;
                ahi[mt][0] = __float_as_uint(Ah[r0]);
                ahi[mt][1] = __float_as_uint(Ah[r8]);
                ahi[mt][2] = __float_as_uint(Ah[r0 + 4]);
                ahi[mt][3] = __float_as_uint(Ah[r8 + 4]);
                alo[mt][0] = __float_as_uint(Al[r0]);
                alo[mt][1] = __float_as_uint(Al[r8]);
                alo[mt][2] = __float_as_uint(Al[r0 + 4]);
                alo[mt][3] = __float_as_uint(Al[r8 + 4]);
            }
            uint32_t bhi[8][2], blo[8][2];
            #pragma unroll
            for (int nt = 0; nt < 8; nt++) {
                int n0 = (wn + nt * 8 + gr) * AST + kk + gc;
                bhi[nt][0] = __float_as_uint(Bh[n0]);
                bhi[nt][1] = __float_as_uint(Bh[n0 + 4]);
                blo[nt][0] = __float_as_uint(Bl[n0]);
                blo[nt][1] = __float_as_uint(Bl[n0 + 4]);
            }
            #pragma unroll
            for (int mt = 0; mt < 2; mt++)
                #pragma unroll
                for (int nt = 0; nt < 8; nt++) {
                    float* d = acc[mt][nt];
                    MMA_TF32(d[0], d[1], d[2], d[3],
                             alo[mt][0], alo[mt][1], alo[mt][2], alo[mt][3],
                             bhi[nt][0], bhi[nt][1]);
                    MMA_TF32(d[0], d[1], d[2], d[3],
                             ahi[mt][0], ahi[mt][1], ahi[mt][2], ahi[mt][3],
                             blo[nt][0], blo[nt][1]);
                    MMA_TF32(d[0], d[1], d[2], d[3],
                             ahi[mt][0], ahi[mt][1], ahi[mt][2], ahi[mt][3],
                             bhi[nt][0], bhi[nt][1]);
                }
        }
    }

    #pragma unroll
    for (int mt = 0; mt < 2; mt++) {
        #pragma unroll
        for (int nt = 0; nt < 8; nt++) {
            int m0 = bm + wm + mt * 16 + gr;
            int n0 = bn + wn + nt * 8 + gc * 2;
            #pragma unroll
            for (int half = 0; half < 2; half++) {
                int m = m0 + half * 8;
                #pragma unroll
                for (int cc = 0; cc < 2; cc++) {
                    int n = n0 + cc;
                    float v = acc[mt][nt][half * 2 + cc] + bias[n];
                    if (mode <= 2) {
                        int b = m >> 11;
                        int s = m & (SS - 1);
                        int h = n >> 6;
                        int d = n & (HD - 1);
                        Cp[(((size_t)b * NH + h) * SS + s) * HD + d] = v;
                    } else {
                        Cp[(size_t)m * D_MODEL + n] = v;
                    }
                }
            }
        }
    }
}

// ============================================================================
// Tensor-core flash attention (bf16-split-3 on mma.sync m16n8k16).
// Block = 128 threads = 4 warps; 64 query rows (16/warp), KT=64 kv per tile.
// smem (uint32 bf16-pair units, row stride 36 => conflict-free frags):
//   Kh,Kl:  [kv=64][d pairs]   VTh,VTl: [d=64][kv pairs]   Ph,Pl: [q=64][kv pairs]
// ============================================================================
#define PST 36                              // pair stride per row
#define ATTN_SMEM (6 * 64 * PST * 4)        // 55296 B

__global__ __launch_bounds__(128)
void attn_kernel(const int* __restrict__ mask)
{
    extern __shared__ __align__(16) uint32_t smw[];
    uint32_t* Kh  = smw;
    uint32_t* Kl  = smw + 1 * 64 * PST;
    uint32_t* VTh = smw + 2 * 64 * PST;
    uint32_t* VTl = smw + 3 * 64 * PST;
    uint32_t* Ph  = smw + 4 * 64 * PST;
    uint32_t* Pl  = smw + 5 * 64 * PST;
    __nv_bfloat16* VThb = (__nv_bfloat16*)VTh;
    __nv_bfloat16* VTlb = (__nv_bfloat16*)VTl;

    const int t    = threadIdx.x;
    const int wid  = t >> 5;
    const int lane = t & 31;
    const int gr   = lane >> 2;
    const int gc   = lane & 3;
    const int wm   = wid * 16;             // warp's query-row offset in tile
    const int q0   = blockIdx.x * 64;
    const int h    = blockIdx.y;
    const int b    = blockIdx.z;
    const float scale = 0.125f;

    const float* qbase = g_q + ((size_t)(b * NH + h) * SS) * HD;
    const float* kbase = g_k + ((size_t)(b * NH + h) * SS) * HD;
    const float* vbase = g_v + ((size_t)(b * NH + h) * SS) * HD;

    // Q fragments (rows wm+gr, wm+gr+8), split bf16 hi/lo, packed pairs.
    uint32_t qh[4][4], ql[4][4];
    {
        const float* qr0 = qbase + (size_t)(q0 + wm + gr) * HD;
        const float* qr1 = qr0 + 8 * HD;
        #pragma unroll
        for (int ks = 0; ks < 4; ks++) {
            int p0 = ks * 8 + gc;          // pair indices
            int p1 = p0 + 4;
            bsplit2(qr0[2*p0], qr0[2*p0+1], qh[ks][0], ql[ks][0]);
            bsplit2(qr1[2*p0], qr1[2*p0+1], qh[ks][1], ql[ks][1]);
            bsplit2(qr0[2*p1], qr0[2*p1+1], qh[ks][2], ql[ks][2]);
            bsplit2(qr1[2*p1], qr1[2*p1+1], qh[ks][3], ql[ks][3]);
        }
    }

    float oacc[8][4];
    #pragma unroll
    for (int dt = 0; dt < 8; dt++)
        #pragma unroll
        for (int r = 0; r < 4; r++) oacc[dt][r] = 0.f;
    float m0 = -1e30f, m1 = -1e30f, l0 = 0.f, l1 = 0.f;

    for (int k0 = 0; k0 < SS; k0 += 64) {
        __syncthreads();   // previous tile's PV done before overwriting K/VT

        // ---- load K tile (split, pairs) + V tile (split, transposed) ----
        #pragma unroll
        for (int i = 0; i < 8; i++) {
            int lin = i * 128 + t;          // 0..1023 float4 units
            int row = lin >> 4;             // kv row 0..63
            int c4  = (lin & 15) << 2;      // d col 0..60
            float4 kv4 = *(const float4*)(kbase + (size_t)(k0 + row) * HD + c4);
            uint32_t h0, l0w, h1, l1w;
            bsplit2(kv4.x, kv4.y, h0, l0w);
            bsplit2(kv4.z, kv4.w, h1, l1w);
            int wi = row * PST + (c4 >> 1);
            Kh[wi] = h0; Kh[wi + 1] = h1;
            Kl[wi] = l0w; Kl[wi + 1] = l1w;

            float4 vv4 = *(const float4*)(vbase + (size_t)(k0 + row) * HD + c4);
            __nv_bfloat16 vh, vl;
            #pragma unroll
            for (int e = 0; e < 4; e++) {
                float x = (e == 0) ? vv4.x : (e == 1) ? vv4.y : (e == 2) ? vv4.z : vv4.w;
                vh = __float2bfloat16_rn(x);
                vl = __float2bfloat16_rn(x - __bfloat162float(vh));
                VThb[(c4 + e) * (2 * PST) + row] = vh;
                VTlb[(c4 + e) * (2 * PST) + row] = vl;
            }
        }
        __syncthreads();

        // ---- QK^T: scores c[8][4], m16n8k16 x 4 ksteps x 3 products ----
        float c[8][4];
        #pragma unroll
        for (int nt = 0; nt < 8; nt++)
            #pragma unroll
            for (int r = 0; r < 4; r++) c[nt][r] = 0.f;

        #pragma unroll
        for (int ks = 0; ks < 4; ks++) {
            #pragma unroll
            for (int nt = 0; nt < 8; nt++) {
                int bi = (nt * 8 + gr) * PST + ks * 8 + gc;
                uint32_t bh0 = Kh[bi], bh1 = Kh[bi + 4];
                uint32_t bl0 = Kl[bi], bl1 = Kl[bi + 4];
                MMA_BF16(c[nt], qh[ks][0], qh[ks][1], qh[ks][2], qh[ks][3], bl0, bl1);
                MMA_BF16(c[nt], ql[ks][0], ql[ks][1], ql[ks][2], ql[ks][3], bh0, bh1);
                MMA_BF16(c[nt], qh[ks][0], qh[ks][1], qh[ks][2], qh[ks][3], bh0, bh1);
            }
        }

        // ---- mask + scale ----
        const int* mrow0 = mask + (size_t)(q0 + wm + gr) * SS + k0;
        const int* mrow1 = mrow0 + 8 * SS;
        #pragma unroll
        for (int nt = 0; nt < 8; nt++) {
            int col = nt * 8 + 2 * gc;
            int2 mv0 = *(const int2*)(mrow0 + col);
            int2 mv1 = *(const int2*)(mrow1 + col);
            c[nt][0] = mv0.x ? c[nt][0] * scale : -10000.f;
            c[nt][1] = mv0.y ? c[nt][1] * scale : -10000.f;
            c[nt][2] = mv1.x ? c[nt][2] * scale : -10000.f;
            c[nt][3] = mv1.y ? c[nt][3] * scale : -10000.f;
        }

        // ---- online softmax ----
        float mx0 = -1e30f, mx1 = -1e30f;
        #pragma unroll
        for (int nt = 0; nt < 8; nt++) {
            mx0 = fmaxf(mx0, fmaxf(c[nt][0], c[nt][1]));
            mx1 = fmaxf(mx1, fmaxf(c[nt][2], c[nt][3]));
        }
        mx0 = fmaxf(mx0, __shfl_xor_sync(0xFFFFFFFF, mx0, 1));
        mx0 = fmaxf(mx0, __shfl_xor_sync(0xFFFFFFFF, mx0, 2));
        mx1 = fmaxf(mx1, __shfl_xor_sync(0xFFFFFFFF, mx1, 1));
        mx1 = fmaxf(mx1, __shfl_xor_sync(0xFFFFFFFF, mx1, 2));

        float mn0 = fmaxf(m0, mx0), mn1 = fmaxf(m1, mx1);
        float al0 = __expf(m0 - mn0), al1 = __expf(m1 - mn1);
        l0 *= al0; l1 *= al1;
        #pragma unroll
        for (int dt = 0; dt < 8; dt++) {
            oacc[dt][0] *= al0; oacc[dt][1] *= al0;
            oacc[dt][2] *= al1; oacc[dt][3] *= al1;
        }

        float s0 = 0.f, s1 = 0.f;
        #pragma unroll
        for (int nt = 0; nt < 8; nt++) {
            c[nt][0] = __expf(c[nt][0] - mn0);
            c[nt][1] = __expf(c[nt][1] - mn0);
            c[nt][2] = __expf(c[nt][2] - mn1);
            c[nt][3] = __expf(c[nt][3] - mn1);
            s0 += c[nt][0] + c[nt][1];
            s1 += c[nt][2] + c[nt][3];
        }
        s0 += __shfl_xor_sync(0xFFFFFFFF, s0, 1);
        s0 += __shfl_xor_sync(0xFFFFFFFF, s0, 2);
        s1 += __shfl_xor_sync(0xFFFFFFFF, s1, 1);
        s1 += __shfl_xor_sync(0xFFFFFFFF, s1, 2);
        l0 += s0; l1 += s1;
        m0 = mn0; m1 = mn1;

        // ---- stage P (split bf16) ----
        #pragma unroll
        for (int nt = 0; nt < 8; nt++) {
            uint32_t ph, pl;
            int pi0 = (wm + gr) * PST + nt * 4 + gc;
            bsplit2(c[nt][0], c[nt][1], ph, pl);
            Ph[pi0] = ph; Pl[pi0] = pl;
            int pi1 = pi0 + 8 * PST;
            bsplit2(c[nt][2], c[nt][3], ph, pl);
            Ph[pi1] = ph; Pl[pi1] = pl;
        }
        __syncthreads();

        // ---- P @ V ----
        #pragma unroll
        for (int ks = 0; ks < 4; ks++) {
            int ai = (wm + gr) * PST + ks * 8 + gc;
            uint32_t pah0 = Ph[ai],           pal0 = Pl[ai];
            uint32_t pah1 = Ph[ai + 8 * PST], pal1 = Pl[ai + 8 * PST];
            uint32_t pah2 = Ph[ai + 4],       pal2 = Pl[ai + 4];
            uint32_t pah3 = Ph[ai + 8 * PST + 4], pal3 = Pl[ai + 8 * PST + 4];
            #pragma unroll
            for (int dt = 0; dt < 8; dt++) {
                int bi = (dt * 8 + gr) * PST + ks * 8 + gc;
                uint32_t bh0 = VTh[bi], bh1 = VTh[bi + 4];
                uint32_t bl0 = VTl[bi], bl1 = VTl[bi + 4];
                MMA_BF16(oacc[dt], pah0, pah1, pah2, pah3, bl0, bl1);
                MMA_BF16(oacc[dt], pal0, pal1, pal2, pal3, bh0, bh1);
                MMA_BF16(oacc[dt], pah0, pah1, pah2, pah3, bh0, bh1);
            }
        }
    }

    // ---- normalize + write [B,S,D] ----
    float inv0 = 1.f / l0, inv1 = 1.f / l1;
    float* orow0 = g_attn + ((size_t)b * SS + q0 + wm + gr) * D_MODEL + h * HD;
    float* orow1 = orow0 + 8 * D_MODEL;
    #pragma unroll
    for (int dt = 0; dt < 8; dt++) {
        int col = dt * 8 + 2 * gc;
        float2 o0 = make_float2(oacc[dt][0] * inv0, oacc[dt][1] * inv0);
        float2 o1 = make_float2(oacc[dt][2] * inv1, oacc[dt][3] * inv1);
        *(float2*)(orow0 + col) = o0;
        *(float2*)(orow1 + col) = o1;
    }
}

// ============================================================================
extern "C" void kernel_launch(void* const* d_in, const int* in_sizes, int n_in,
                              void* d_out, int out_size)
{
    const float* q    = (const float*)d_in[0];
    const float* k    = (const float*)d_in[1];
    const float* v    = (const float*)d_in[2];
    const int*   mask = (const int*)  d_in[3];
    const float* wq   = (const float*)d_in[4];
    const float* bq   = (const float*)d_in[5];
    const float* wk   = (const float*)d_in[6];
    const float* bk   = (const float*)d_in[7];
    const float* wv   = (const float*)d_in[8];
    const float* bv   = (const float*)d_in[9];
    const float* wo   = (const float*)d_in[10];
    const float* bo   = (const float*)d_in[11];
    float* out = (float*)d_out;

    cudaFuncSetAttribute(tc_gemm, cudaFuncAttributeMaxDynamicSharedMemorySize, GEMM_SMEM);
    cudaFuncSetAttribute(attn_kernel, cudaFuncAttributeMaxDynamicSharedMemorySize, ATTN_SMEM);

    dim3 gg(D_MODEL / 128, MROWS / 128);   // (8, 32)
    tc_gemm<<<gg, 256, GEMM_SMEM>>>(q, wq, bq, nullptr, 0);
    tc_gemm<<<gg, 256, GEMM_SMEM>>>(k, wk, bk, nullptr, 1);
    tc_gemm<<<gg, 256, GEMM_SMEM>>>(v, wv, bv, nullptr, 2);
    attn_kernel<<<dim3(SS / 64, NH, BB), 128, ATTN_SMEM>>>(mask);
    tc_gemm<<<gg, 256, GEMM_SMEM>>>(nullptr, wo, bo, out, 3);
}

// round 8
// speedup vs baseline: 2.3875x; 1.2004x over previous
#include <cuda_runtime.h>
#include <cuda_bf16.h>
#include <cstdint>
#include <math.h>

#define D_MODEL 1024
#define NH 16
#define HD 64
#define BB 2
#define SS 2048
#define MROWS (BB*SS)   // 4096
#define NPAIR (MROWS*D_MODEL/2)   // 2M uint32 pairs per tensor

// Scratch (allocation-free __device__ globals)
// Split-bf16 pair arrays: hi/lo packed as bf16x2 (pairs along last dim)
__device__ uint32_t g_qh[NPAIR], g_ql[NPAIR];     // [B,H,S,Dh/2]
__device__ uint32_t g_kh[NPAIR], g_kl[NPAIR];     // [B,H,S,Dh/2]
__device__ uint32_t g_vh[NPAIR], g_vl[NPAIR];     // [B,H,S,Dh/2]
__device__ uint32_t g_vth[NPAIR], g_vtl[NPAIR];   // [B,H,Dh,S/2]  (V transposed)
__device__ float    g_attn[(size_t)MROWS*D_MODEL];// [B,S,D]

// ============================================================================
// helpers
// ============================================================================
__device__ __forceinline__ uint32_t pack_bf2(__nv_bfloat16 a, __nv_bfloat16 b) {
    __nv_bfloat162 v; v.x = a; v.y = b;
    return *(uint32_t*)&v;
}
// split (x,y) into packed bf16x2 hi + residual lo
__device__ __forceinline__ void bsplit2(float x, float y, uint32_t& hi, uint32_t& lo) {
    __nv_bfloat16 hx = __float2bfloat16_rn(x);
    __nv_bfloat16 hy = __float2bfloat16_rn(y);
    __nv_bfloat16 lx = __float2bfloat16_rn(x - __bfloat162float(hx));
    __nv_bfloat16 ly = __float2bfloat16_rn(y - __bfloat162float(hy));
    hi = pack_bf2(hx, hy);
    lo = pack_bf2(lx, ly);
}

// mma.sync m16n8k16 bf16: D += A*B (A row-major 16x16, B col-major 16x8)
#define MMA_BF16(dd, a0,a1,a2,a3, b0,b1) \
    asm volatile( \
        "mma.sync.aligned.m16n8k16.row.col.f32.bf16.bf16.f32 " \
        "{%0,%1,%2,%3}, {%4,%5,%6,%7}, {%8,%9}, {%0,%1,%2,%3};" \
        : "+f"((dd)[0]), "+f"((dd)[1]), "+f"((dd)[2]), "+f"((dd)[3]) \
        : "r"(a0), "r"(a1), "r"(a2), "r"(a3), "r"(b0), "r"(b1))

// ============================================================================
// Split-bf16 tensor-core GEMM: C[M,N] = A[M,K] @ W[N,K]^T + bias
// M=4096, N=K=1024. Block tile 128x128, K-chunk 32 (2 k16 steps).
// 3 products: ah*bh + ah*bl + al*bh  (~16-bit effective mantissa).
// mode 0/1/2: write split-bf16 pairs (q/k/v) in [B,H,S,Dh]; mode 3: f32 out.
// ============================================================================
#define GP 18   // pair stride per row (16 + 2 pad)

__global__ __launch_bounds__(256)
void tc_gemm(const float* __restrict__ A, const float* __restrict__ W,
             const float* __restrict__ bias, float* __restrict__ Cout, int mode)
{
    __shared__ uint32_t sh[4 * 128 * GP];   // 36,864 B
    uint32_t* Ah = sh;
    uint32_t* Al = sh + 1 * 128 * GP;
    uint32_t* Bh = sh + 2 * 128 * GP;
    uint32_t* Bl = sh + 3 * 128 * GP;

    const int tid  = threadIdx.x;
    const int wid  = tid >> 5;
    const int lane = tid & 31;
    const int wm   = (wid & 3) << 5;
    const int wn   = (wid >> 2) << 6;
    const int gr   = lane >> 2;
    const int gc   = lane & 3;

    const float* Ap = (mode == 3) ? g_attn : A;
    const int bm = blockIdx.y * 128;
    const int bn = blockIdx.x * 128;

    float acc[2][8][4];
    #pragma unroll
    for (int mt = 0; mt < 2; mt++)
        #pragma unroll
        for (int nt = 0; nt < 8; nt++)
            #pragma unroll
            for (int r = 0; r < 4; r++) acc[mt][nt][r] = 0.f;

    for (int k0 = 0; k0 < D_MODEL; k0 += 32) {
        __syncthreads();
        #pragma unroll
        for (int i = 0; i < 4; i++) {
            int lin = i * 256 + tid;          // 0..1023
            int row = lin >> 3;               // 0..127
            int c4  = (lin & 7) << 2;         // 0..28 (f32 col)
            int so  = row * GP + (c4 >> 1);   // pair index

            float4 a = *(const float4*)(Ap + (size_t)(bm + row) * D_MODEL + k0 + c4);
            uint32_t h0, l0, h1, l1;
            bsplit2(a.x, a.y, h0, l0);
            bsplit2(a.z, a.w, h1, l1);
            *(uint2*)&Ah[so] = make_uint2(h0, h1);
            *(uint2*)&Al[so] = make_uint2(l0, l1);

            float4 b = *(const float4*)(W + (size_t)(bn + row) * D_MODEL + k0 + c4);
            bsplit2(b.x, b.y, h0, l0);
            bsplit2(b.z, b.w, h1, l1);
            *(uint2*)&Bh[so] = make_uint2(h0, h1);
            *(uint2*)&Bl[so] = make_uint2(l0, l1);
        }
        __syncthreads();

        #pragma unroll
        for (int ks = 0; ks < 2; ks++) {
            const int kp = ks * 8 + gc;
            uint32_t ah[2][4], al[2][4];
            #pragma unroll
            for (int mt = 0; mt < 2; mt++) {
                int r0 = (wm + mt * 16 + gr) * GP + kp;
                int r8 = r0 + 8 * GP;
                ah[mt][0] = Ah[r0]; ah[mt][1] = Ah[r8];
                ah[mt][2] = Ah[r0 + 4]; ah[mt][3] = Ah[r8 + 4];
                al[mt][0] = Al[r0]; al[mt][1] = Al[r8];
                al[mt][2] = Al[r0 + 4]; al[mt][3] = Al[r8 + 4];
            }
            uint32_t bh[8][2], bl[8][2];
            #pragma unroll
            for (int nt = 0; nt < 8; nt++) {
                int n0 = (wn + nt * 8 + gr) * GP + kp;
                bh[nt][0] = Bh[n0]; bh[nt][1] = Bh[n0 + 4];
                bl[nt][0] = Bl[n0]; bl[nt][1] = Bl[n0 + 4];
            }
            #pragma unroll
            for (int mt = 0; mt < 2; mt++)
                #pragma unroll
                for (int nt = 0; nt < 8; nt++) {
                    float* d = acc[mt][nt];
                    MMA_BF16(d, ah[mt][0], ah[mt][1], ah[mt][2], ah[mt][3],
                             bl[nt][0], bl[nt][1]);
                    MMA_BF16(d, al[mt][0], al[mt][1], al[mt][2], al[mt][3],
                             bh[nt][0], bh[nt][1]);
                    MMA_BF16(d, ah[mt][0], ah[mt][1], ah[mt][2], ah[mt][3],
                             bh[nt][0], bh[nt][1]);
                }
        }
    }

    // epilogue
    uint32_t* Hp = (mode == 0) ? g_qh : (mode == 1) ? g_kh : g_vh;
    uint32_t* Lp = (mode == 0) ? g_ql : (mode == 1) ? g_kl : g_vl;
    #pragma unroll
    for (int mt = 0; mt < 2; mt++) {
        #pragma unroll
        for (int nt = 0; nt < 8; nt++) {
            int m0 = bm + wm + mt * 16 + gr;
            int n0 = bn + wn + nt * 8 + gc * 2;   // even
            float b0 = bias[n0], b1 = bias[n0 + 1];
            #pragma unroll
            for (int half = 0; half < 2; half++) {
                int m = m0 + half * 8;
                float v0 = acc[mt][nt][half * 2 + 0] + b0;
                float v1 = acc[mt][nt][half * 2 + 1] + b1;
                if (mode <= 2) {
                    int b = m >> 11;
                    int s = m & (SS - 1);
                    int h = n0 >> 6;
                    int d = n0 & (HD - 1);
                    size_t pidx = (((size_t)(b * NH + h) * SS + s) * HD + d) >> 1;
                    uint32_t hi, lo;
                    bsplit2(v0, v1, hi, lo);
                    Hp[pidx] = hi;
                    Lp[pidx] = lo;
                } else {
                    *(float2*)(Cout + (size_t)m * D_MODEL + n0) = make_float2(v0, v1);
                }
            }
        }
    }
}

// ============================================================================
// V transpose: g_vh/g_vl [b,h,s,d-pairs] -> g_vth/g_vtl [b,h,d,s-pairs]
// Block: 64 s-rows x 64 d. Grid (S/64, NH, BB).
// ============================================================================
#define TP 36   // pair stride (32 + 4 pad), 144B = 9*16 aligned

__global__ __launch_bounds__(128)
void vtrans_kernel()
{
    __shared__ uint32_t th[64 * TP], tl[64 * TP];   // 2 x 9216 B
    const int t  = threadIdx.x;
    const int s0 = blockIdx.x * 64;
    const int h  = blockIdx.y;
    const int b  = blockIdx.z;
    const size_t bh = (size_t)(b * NH + h);

    const uint4* src_h = (const uint4*)g_vh;
    const uint4* src_l = (const uint4*)g_vl;
    #pragma unroll
    for (int i = 0; i < 4; i++) {
        int lin = i * 128 + t;            // 0..511
        int row = lin >> 3;               // 0..63
        int c4  = (lin & 7) << 2;         // pair idx 0..28
        size_t si = (bh * SS + s0 + row) * 8 + (c4 >> 2);
        *(uint4*)&th[row * TP + c4] = src_h[si];
        *(uint4*)&tl[row * TP + c4] = src_l[si];
    }
    __syncthreads();

    const __nv_bfloat16* thb = (const __nv_bfloat16*)th;
    const __nv_bfloat16* tlb = (const __nv_bfloat16*)tl;
    const int sp = t & 31;
    const int dr = t >> 2 >> 3;           // t>>5: 0..3
    #pragma unroll
    for (int i = 0; i < 16; i++) {
        int d = i * 4 + dr;               // 0..63
        __nv_bfloat16 h0 = thb[(2 * sp) * (2 * TP) + d];
        __nv_bfloat16 h1 = thb[(2 * sp + 1) * (2 * TP) + d];
        __nv_bfloat16 l0 = tlb[(2 * sp) * (2 * TP) + d];
        __nv_bfloat16 l1 = tlb[(2 * sp + 1) * (2 * TP) + d];
        size_t di = (bh * HD + d) * (SS / 2) + (s0 >> 1) + sp;
        g_vth[di] = pack_bf2(h0, h1);
        g_vtl[di] = pack_bf2(l0, l1);
    }
}

// ============================================================================
// Tensor-core flash attention. Block = 128 threads = 4 warps, 64 q rows
// (16/warp), KT=64. All operands pre-split bf16 in gmem; P stays in registers
// (QK D-fragment == PV A-fragment layout).
// ============================================================================
#define PST 36

__global__ __launch_bounds__(128)
void attn_kernel(const int* __restrict__ mask)
{
    __shared__ uint32_t Kh[64 * PST], Kl[64 * PST], Vh[64 * PST], Vl[64 * PST]; // 36,864 B

    const int t    = threadIdx.x;
    const int wid  = t >> 5;
    const int lane = t & 31;
    const int gr   = lane >> 2;
    const int gc   = lane & 3;
    const int wm   = wid * 16;
    const int q0   = blockIdx.x * 64;
    const int h    = blockIdx.y;
    const int b    = blockIdx.z;
    const float scale = 0.125f;

    const size_t bh = (size_t)(b * NH + h);
    const uint32_t* qhp = g_qh + bh * SS * (HD / 2);
    const uint32_t* qlp = g_ql + bh * SS * (HD / 2);
    const uint32_t* khp = g_kh + bh * SS * (HD / 2);
    const uint32_t* klp = g_kl + bh * SS * (HD / 2);
    const uint32_t* vhp = g_vth + bh * HD * (SS / 2);
    const uint32_t* vlp = g_vtl + bh * HD * (SS / 2);

    // Q fragments direct from split pairs
    uint32_t qh[4][4], ql[4][4];
    {
        int r0 = (q0 + wm + gr) * 32;
        int r1 = r0 + 8 * 32;
        #pragma unroll
        for (int ks = 0; ks < 4; ks++) {
            int p = ks * 8 + gc;
            qh[ks][0] = qhp[r0 + p];     qh[ks][1] = qhp[r1 + p];
            qh[ks][2] = qhp[r0 + p + 4]; qh[ks][3] = qhp[r1 + p + 4];
            ql[ks][0] = qlp[r0 + p];     ql[ks][1] = qlp[r1 + p];
            ql[ks][2] = qlp[r0 + p + 4]; ql[ks][3] = qlp[r1 + p + 4];
        }
    }

    float oacc[8][4];
    #pragma unroll
    for (int dt = 0; dt < 8; dt++)
        #pragma unroll
        for (int r = 0; r < 4; r++) oacc[dt][r] = 0.f;
    float m0 = -1e30f, m1 = -1e30f, l0 = 0.f, l1 = 0.f;

    for (int k0 = 0; k0 < SS; k0 += 64) {
        __syncthreads();   // prior PV done before overwriting tiles

        // bulk copy K and V^T tiles (bf16 pairs, no conversion)
        #pragma unroll
        for (int i = 0; i < 4; i++) {
            int lin = i * 128 + t;          // 0..511
            int row = lin >> 3;             // 0..63 (kv for K, d for VT)
            int c4  = (lin & 7) << 2;       // pair 0..28
            int so  = row * PST + c4;
            *(uint4*)&Kh[so] = *(const uint4*)(khp + (size_t)(k0 + row) * 32 + c4);
            *(uint4*)&Kl[so] = *(const uint4*)(klp + (size_t)(k0 + row) * 32 + c4);
            *(uint4*)&Vh[so] = *(const uint4*)(vhp + (size_t)row * (SS / 2) + (k0 >> 1) + c4);
            *(uint4*)&Vl[so] = *(const uint4*)(vlp + (size_t)row * (SS / 2) + (k0 >> 1) + c4);
        }
        __syncthreads();

        // ---- QK^T ----
        float c[8][4];
        #pragma unroll
        for (int nt = 0; nt < 8; nt++)
            #pragma unroll
            for (int r = 0; r < 4; r++) c[nt][r] = 0.f;

        #pragma unroll
        for (int ks = 0; ks < 4; ks++) {
            #pragma unroll
            for (int nt = 0; nt < 8; nt++) {
                int bi = (nt * 8 + gr) * PST + ks * 8 + gc;
                uint32_t bh0 = Kh[bi], bh1 = Kh[bi + 4];
                uint32_t bl0 = Kl[bi], bl1 = Kl[bi + 4];
                MMA_BF16(c[nt], qh[ks][0], qh[ks][1], qh[ks][2], qh[ks][3], bl0, bl1);
                MMA_BF16(c[nt], ql[ks][0], ql[ks][1], ql[ks][2], ql[ks][3], bh0, bh1);
                MMA_BF16(c[nt], qh[ks][0], qh[ks][1], qh[ks][2], qh[ks][3], bh0, bh1);
            }
        }

        // ---- mask + scale ----
        const int* mrow0 = mask + (size_t)(q0 + wm + gr) * SS + k0;
        const int* mrow1 = mrow0 + 8 * SS;
        #pragma unroll
        for (int nt = 0; nt < 8; nt++) {
            int col = nt * 8 + 2 * gc;
            int2 mv0 = *(const int2*)(mrow0 + col);
            int2 mv1 = *(const int2*)(mrow1 + col);
            c[nt][0] = mv0.x ? c[nt][0] * scale : -10000.f;
            c[nt][1] = mv0.y ? c[nt][1] * scale : -10000.f;
            c[nt][2] = mv1.x ? c[nt][2] * scale : -10000.f;
            c[nt][3] = mv1.y ? c[nt][3] * scale : -10000.f;
        }

        // ---- online softmax (rows live in quads) ----
        float mx0 = -1e30f, mx1 = -1e30f;
        #pragma unroll
        for (int nt = 0; nt < 8; nt++) {
            mx0 = fmaxf(mx0, fmaxf(c[nt][0], c[nt][1]));
            mx1 = fmaxf(mx1, fmaxf(c[nt][2], c[nt][3]));
        }
        mx0 = fmaxf(mx0, __shfl_xor_sync(0xFFFFFFFF, mx0, 1));
        mx0 = fmaxf(mx0, __shfl_xor_sync(0xFFFFFFFF, mx0, 2));
        mx1 = fmaxf(mx1, __shfl_xor_sync(0xFFFFFFFF, mx1, 1));
        mx1 = fmaxf(mx1, __shfl_xor_sync(0xFFFFFFFF, mx1, 2));

        float mn0 = fmaxf(m0, mx0), mn1 = fmaxf(m1, mx1);
        float al0 = __expf(m0 - mn0), al1 = __expf(m1 - mn1);
        l0 *= al0; l1 *= al1;
        #pragma unroll
        for (int dt = 0; dt < 8; dt++) {
            oacc[dt][0] *= al0; oacc[dt][1] *= al0;
            oacc[dt][2] *= al1; oacc[dt][3] *= al1;
        }

        float s0 = 0.f, s1 = 0.f;
        #pragma unroll
        for (int nt = 0; nt < 8; nt++) {
            c[nt][0] = __expf(c[nt][0] - mn0);
            c[nt][1] = __expf(c[nt][1] - mn0);
            c[nt][2] = __expf(c[nt][2] - mn1);
            c[nt][3] = __expf(c[nt][3] - mn1);
            s0 += c[nt][0] + c[nt][1];
            s1 += c[nt][2] + c[nt][3];
        }
        s0 += __shfl_xor_sync(0xFFFFFFFF, s0, 1);
        s0 += __shfl_xor_sync(0xFFFFFFFF, s0, 2);
        s1 += __shfl_xor_sync(0xFFFFFFFF, s1, 1);
        s1 += __shfl_xor_sync(0xFFFFFFFF, s1, 2);
        l0 += s0; l1 += s1;
        m0 = mn0; m1 = mn1;

        // ---- P @ V : P packed in registers (D-frag == A-frag layout) ----
        #pragma unroll
        for (int ks = 0; ks < 4; ks++) {
            uint32_t pah[4], pal[4];
            bsplit2(c[2*ks][0],   c[2*ks][1],   pah[0], pal[0]);
            bsplit2(c[2*ks][2],   c[2*ks][3],   pah[1], pal[1]);
            bsplit2(c[2*ks+1][0], c[2*ks+1][1], pah[2], pal[2]);
            bsplit2(c[2*ks+1][2], c[2*ks+1][3], pah[3], pal[3]);
            #pragma unroll
            for (int dt = 0; dt < 8; dt++) {
                int bi = (dt * 8 + gr) * PST + ks * 8 + gc;
                uint32_t bh0 = Vh[bi], bh1 = Vh[bi + 4];
                uint32_t bl0 = Vl[bi], bl1 = Vl[bi + 4];
                MMA_BF16(oacc[dt], pah[0], pah[1], pah[2], pah[3], bl0, bl1);
                MMA_BF16(oacc[dt], pal[0], pal[1], pal[2], pal[3], bh0, bh1);
                MMA_BF16(oacc[dt], pah[0], pah[1], pah[2], pah[3], bh0, bh1);
            }
        }
    }

    // ---- normalize + write [B,S,D] ----
    float inv0 = 1.f / l0, inv1 = 1.f / l1;
    float* orow0 = g_attn + ((size_t)b * SS + q0 + wm + gr) * D_MODEL + h * HD;
    float* orow1 = orow0 + 8 * D_MODEL;
    #pragma unroll
    for (int dt = 0; dt < 8; dt++) {
        int col = dt * 8 + 2 * gc;
        *(float2*)(orow0 + col) = make_float2(oacc[dt][0] * inv0, oacc[dt][1] * inv0);
        *(float2*)(orow1 + col) = make_float2(oacc[dt][2] * inv1, oacc[dt][3] * inv1);
    }
}

// ============================================================================
extern "C" void kernel_launch(void* const* d_in, const int* in_sizes, int n_in,
                              void* d_out, int out_size)
{
    const float* q    = (const float*)d_in[0];
    const float* k    = (const float*)d_in[1];
    const float* v    = (const float*)d_in[2];
    const int*   mask = (const int*)  d_in[3];
    const float* wq   = (const float*)d_in[4];
    const float* bq   = (const float*)d_in[5];
    const float* wk   = (const float*)d_in[6];
    const float* bk   = (const float*)d_in[7];
    const float* wv   = (const float*)d_in[8];
    const float* bv   = (const float*)d_in[9];
    const float* wo   = (const float*)d_in[10];
    const float* bo   = (const float*)d_in[11];
    float* out = (float*)d_out;

    dim3 gg(D_MODEL / 128, MROWS / 128);   // (8, 32)
    tc_gemm<<<gg, 256>>>(q, wq, bq, nullptr, 0);
    tc_gemm<<<gg, 256>>>(k, wk, bk, nullptr, 1);
    tc_gemm<<<gg, 256>>>(v, wv, bv, nullptr, 2);
    vtrans_kernel<<<dim3(SS / 64, NH, BB), 128>>>();
    attn_kernel<<<dim3(SS / 64, NH, BB), 128>>>(mask);
    tc_gemm<<<gg, 256>>>(nullptr, wo, bo, out, 3);
}